// round 15
// baseline (speedup 1.0000x reference)
#include <cuda_runtime.h>
#include <cstdint>
#include <math.h>

// ---------------- problem constants ----------------
#define NB     4
#define LSEQ   8192
#define DMODEL 256
#define NHEAD  8
#define HDIM   32
#define WNW    9
#define PAD    4
#define PLEN   8200          // L + 2*PAD
#define NROW   32800         // NB * PLEN
#define MROW   32768         // NB * LSEQ
#define ATT_SCALE 0.17677669529663687f  // 1/sqrt(32)

// ---------------- scratch ----------------
__device__ float g_qkv[(size_t)NROW * 768];
__device__ float g_posqkv[WNW * 768];
__device__ float g_pp[NHEAD * 81];
__device__ float g_R1[(size_t)NROW * NHEAD * 9];
__device__ float g_R2[(size_t)NROW * NHEAD * 9];
__device__ float g_XX[(size_t)NROW * NHEAD * 17];
__device__ float g_ctx[(size_t)MROW * DMODEL];
__device__ float g_wT[5 * 256 * 256];
__device__ float g_xr[(size_t)MROW * DMODEL];

__device__ __forceinline__ float tf32r(float x) {
    uint32_t u;
    asm("cvt.rna.tf32.f32 %0, %1;" : "=r"(u) : "f"(x));
    return __uint_as_float(u);
}
__device__ __forceinline__ uint32_t smem_u32(const void* p) {
    uint32_t a;
    asm("{ .reg .u64 t; cvta.to.shared.u64 t, %1; cvt.u32.u64 %0, t; }" : "=r"(a) : "l"(p));
    return a;
}

// ---------------- K_prep: round x + transpose/round weights + posproj ----------------
__global__ void __launch_bounds__(256) k_prep(const float* __restrict__ x,
                                              const float* __restrict__ Wq,
                                              const float* __restrict__ Wk,
                                              const float* __restrict__ Wv,
                                              const float* __restrict__ Wo,
                                              const float* __restrict__ Wout,
                                              const float* __restrict__ pos) {
    __shared__ float t[32][33];
    int bid = blockIdx.x;
    int tid = threadIdx.x;
    if (bid < 8192) {
        size_t i = ((size_t)bid * 256 + tid) * 4;
        float4 v = *(const float4*)(x + i);
        v.x = tf32r(v.x); v.y = tf32r(v.y); v.z = tf32r(v.z); v.w = tf32r(v.w);
        *(float4*)(g_xr + i) = v;
        return;
    }
    if (bid < 8512) {
        int rem = bid - 8192;
        int z = rem >> 6;
        int r2 = rem & 63;
        int bx = (r2 & 7) * 32, by = (r2 >> 3) * 32;
        int c = tid & 31, r0 = tid >> 5;
        if (z == 4) {
#pragma unroll
            for (int i = 0; i < 4; i++) {
                int r = r0 + i * 8;
                size_t idx = (size_t)(by + r) * 256 + bx + c;
                g_wT[(size_t)4 * 65536 + idx] = tf32r(Wout[idx]);
            }
            return;
        }
        const float* W = (z == 0) ? Wq : (z == 1) ? Wk : (z == 2) ? Wv : Wo;
#pragma unroll
        for (int i = 0; i < 4; i++) {
            int r = r0 + i * 8;
            t[r][c] = W[(size_t)(by + r) * 256 + bx + c];
        }
        __syncthreads();
#pragma unroll
        for (int i = 0; i < 4; i++) {
            int r = r0 + i * 8;
            g_wT[(size_t)z * 65536 + (size_t)(bx + r) * 256 + by + c] = tf32r(t[c][r]);
        }
        return;
    }
    int tt = (bid - 8512) * 256 + tid;
    int w = tt / 768, j = tt % 768;
    const float* W = (j < 256) ? Wq : ((j < 512) ? Wk : Wv);
    int jj = j & 255;
    const float* p = pos + w * DMODEL;
    float acc = 0.f;
    for (int d = 0; d < DMODEL; d++) acc = fmaf(p[d], W[d * DMODEL + jj], acc);
    g_posqkv[tt] = acc;
}

// ---------------- MODE0 GEMM: qkv projection (R13 known-good) ----------------
__global__ void __launch_bounds__(256) k_tgemm0(const float* __restrict__ Aglob) {
    constexpr int MT = 128;
    extern __shared__ float sm[];
    float* As = sm;                        // [4][2048]
    float* Bs = sm + 4 * 2048;             // [4][4096]
    int tid = threadIdx.x;
    int rb = blockIdx.x * MT;
    const float* Bmat = g_wT + (size_t)blockIdx.y * 65536;

    const float* ap[2]; uint32_t azf[2]; uint32_t aAddr[2];
    const float* bp[4]; uint32_t bAddr[4];
#pragma unroll
    for (int i = 0; i < 2; i++) {
        int id = tid + i * 256;
        int row = id >> 2, c4 = (id & 3) * 4;
        int soff = row * 16 + (c4 ^ (4 * ((row >> 1) & 3)));
        aAddr[i] = smem_u32(&As[soff]);
        int gr = rb + row;
        int b = gr / PLEN;
        int r = gr - b * PLEN;
        int xr = r - PAD;
        bool av = (gr < NROW) && ((unsigned)xr < (unsigned)LSEQ);
        azf[i] = av ? 16u : 0u;
        ap[i] = Aglob + ((size_t)b * LSEQ + (size_t)((unsigned)xr < (unsigned)LSEQ ? xr : 0)) * 256 + c4;
    }
#pragma unroll
    for (int i = 0; i < 4; i++) {
        int id = tid + i * 256;
        int row = id >> 2, c4 = (id & 3) * 4;
        int soff = row * 16 + (c4 ^ (4 * ((row >> 1) & 3)));
        bAddr[i] = smem_u32(&Bs[soff]);
        bp[i] = Bmat + (size_t)row * 256 + c4;
    }

    auto issue = [&](int chunk, int stage) {
        int kb = chunk * 16;
        uint32_t ao = (uint32_t)stage * 8192;
        uint32_t bo = (uint32_t)stage * 16384;
#pragma unroll
        for (int i = 0; i < 2; i++)
            asm volatile("cp.async.cg.shared.global [%0], [%1], 16, %2;"
                         :: "r"(aAddr[i] + ao), "l"(ap[i] + kb), "r"(azf[i]) : "memory");
#pragma unroll
        for (int i = 0; i < 4; i++)
            asm volatile("cp.async.cg.shared.global [%0], [%1], 16;"
                         :: "r"(bAddr[i] + bo), "l"(bp[i] + kb) : "memory");
        asm volatile("cp.async.commit_group;" ::: "memory");
    };

    int lane = tid & 31;
    int w = tid >> 5;
    int wm = (w & 1) * 64;
    int wn = (w >> 1) * 64;
    int gid = lane >> 2;
    int tig = lane & 3;
    int swz = 4 * ((gid >> 1) & 3);

    float c[4][8][4];
#pragma unroll
    for (int mt = 0; mt < 4; mt++)
#pragma unroll
        for (int nt = 0; nt < 8; nt++)
#pragma unroll
            for (int q = 0; q < 4; q++) c[mt][nt][q] = 0.f;

    issue(0, 0); issue(1, 1); issue(2, 2);

#pragma unroll 1
    for (int kc = 0; kc < 16; kc++) {
        if (kc < 14)       { asm volatile("cp.async.wait_group 2;" ::: "memory"); }
        else if (kc == 14) { asm volatile("cp.async.wait_group 1;" ::: "memory"); }
        else               { asm volatile("cp.async.wait_group 0;" ::: "memory"); }
        __syncthreads();
        if (kc + 3 < 16) issue(kc + 3, (kc + 3) & 3);
        const float* Ab = As + (kc & 3) * 2048;
        const float* Bb = Bs + (kc & 3) * 4096;
#pragma unroll
        for (int kh = 0; kh < 2; kh++) {
            int ka = (kh * 8 + tig) ^ swz;
            int kb2 = ka ^ 4;
            uint32_t af[4][4], bf[8][2];
#pragma unroll
            for (int mt = 0; mt < 4; mt++) {
                int mbase = (wm + mt * 16 + gid) * 16;
                af[mt][0] = __float_as_uint(Ab[mbase + ka]);
                af[mt][1] = __float_as_uint(Ab[mbase + 128 + ka]);
                af[mt][2] = __float_as_uint(Ab[mbase + kb2]);
                af[mt][3] = __float_as_uint(Ab[mbase + 128 + kb2]);
            }
#pragma unroll
            for (int nt = 0; nt < 8; nt++) {
                int nbase = (wn + nt * 8 + gid) * 16;
                bf[nt][0] = __float_as_uint(Bb[nbase + ka]);
                bf[nt][1] = __float_as_uint(Bb[nbase + kb2]);
            }
#pragma unroll
            for (int mt = 0; mt < 4; mt++)
#pragma unroll
                for (int nt = 0; nt < 8; nt++) {
                    asm volatile(
                        "mma.sync.aligned.m16n8k8.row.col.f32.tf32.tf32.f32 "
                        "{%0,%1,%2,%3}, {%4,%5,%6,%7}, {%8,%9}, {%0,%1,%2,%3};"
                        : "+f"(c[mt][nt][0]), "+f"(c[mt][nt][1]),
                          "+f"(c[mt][nt][2]), "+f"(c[mt][nt][3])
                        : "r"(af[mt][0]), "r"(af[mt][1]), "r"(af[mt][2]), "r"(af[mt][3]),
                          "r"(bf[nt][0]), "r"(bf[nt][1]));
                }
        }
    }

    int jb = blockIdx.y * 256;
#pragma unroll
    for (int mt = 0; mt < 4; mt++)
#pragma unroll
        for (int rr = 0; rr < 2; rr++) {
            int gr = rb + wm + mt * 16 + gid + rr * 8;
            if (gr >= NROW) continue;
#pragma unroll
            for (int nt = 0; nt < 8; nt++) {
                int col = wn + nt * 8 + 2 * tig;
                *(float2*)(g_qkv + (size_t)gr * 768 + jb + col) =
                    make_float2(c[mt][nt][rr * 2], c[mt][nt][rr * 2 + 1]);
            }
        }
}

// ---------------- K_tail: fused (x + ctx@Wo -> LN1) -> (res@Wout^T + bout + res -> LN2 -> relu) ----------------
// M-tile 64, grid 512. res never touches DRAM (lives in SMEM A2, mma-swizzled chunks).
#define TAIL_SMEM ((4 * 1024 + 4 * 4096 + 16384) * 4)

__global__ void __launch_bounds__(256) k_tail(const float* __restrict__ Actx,
                                              const float* __restrict__ xskip,
                                              const float* __restrict__ bout,
                                              const float* __restrict__ g1,
                                              const float* __restrict__ b1,
                                              const float* __restrict__ g2,
                                              const float* __restrict__ b2,
                                              float* __restrict__ outp) {
    extern __shared__ float sm[];
    float* As = sm;                 // [4][1024]
    float* Bs = sm + 4096;          // [4][4096]
    float* A2 = sm + 4096 + 16384;  // [16][64][16]  (chunk-major, swizzled)
    __shared__ float s_g1[256], s_b1[256], s_g2[256], s_b2[256], s_bo[256];
    __shared__ float s_sum[64][4], s_sq[64][4];

    int tid = threadIdx.x;
    int rb = blockIdx.x * 64;
    s_g1[tid] = g1[tid]; s_b1[tid] = b1[tid];
    s_g2[tid] = g2[tid]; s_b2[tid] = b2[tid];
    s_bo[tid] = bout[tid];

    // cp.async slots: A 1/thread, B 4/thread
    const float* ap; uint32_t aAddr;
    size_t boff[4]; uint32_t bAddr[4];
    {
        int row = tid >> 2, c4 = (tid & 3) * 4;
        int soff = row * 16 + (c4 ^ (4 * ((row >> 1) & 3)));
        aAddr = smem_u32(&As[soff]);
        ap = Actx + (size_t)(rb + row) * 256 + c4;
    }
    const float* BmatA = g_wT + (size_t)3 * 65536;   // Wo^T
    const float* BmatB = g_wT + (size_t)4 * 65536;   // Wout
#pragma unroll
    for (int i = 0; i < 4; i++) {
        int id = tid + i * 256;
        int row = id >> 2, c4 = (id & 3) * 4;
        int soff = row * 16 + (c4 ^ (4 * ((row >> 1) & 3)));
        bAddr[i] = smem_u32(&Bs[soff]);
        boff[i] = (size_t)row * 256 + c4;          // ELEMENT offset (bug fixed)
    }

    auto issueA = [&](int chunk, int stage) {
        int kb = chunk * 16;
        uint32_t ao = (uint32_t)stage * 4096;
        uint32_t bo = (uint32_t)stage * 16384;
        asm volatile("cp.async.cg.shared.global [%0], [%1], 16;"
                     :: "r"(aAddr + ao), "l"(ap + kb) : "memory");
#pragma unroll
        for (int i = 0; i < 4; i++)
            asm volatile("cp.async.cg.shared.global [%0], [%1], 16;"
                         :: "r"(bAddr[i] + bo), "l"(BmatA + boff[i] + kb) : "memory");
        asm volatile("cp.async.commit_group;" ::: "memory");
    };
    auto issueB = [&](int chunk, int stage) {
        int kb = chunk * 16;
        uint32_t bo = (uint32_t)stage * 16384;
#pragma unroll
        for (int i = 0; i < 4; i++)
            asm volatile("cp.async.cg.shared.global [%0], [%1], 16;"
                         :: "r"(bAddr[i] + bo), "l"(BmatB + boff[i] + kb) : "memory");
        asm volatile("cp.async.commit_group;" ::: "memory");
    };

    int lane = tid & 31;
    int w = tid >> 5;
    int wm = (w & 1) * 32;
    int wn = (w >> 1) * 64;
    int gid = lane >> 2;
    int tig = lane & 3;
    int swz = 4 * ((gid >> 1) & 3);

    float c[2][8][4];
#pragma unroll
    for (int mt = 0; mt < 2; mt++)
#pragma unroll
        for (int nt = 0; nt < 8; nt++)
#pragma unroll
            for (int q = 0; q < 4; q++) c[mt][nt][q] = 0.f;

    issueA(0, 0); issueA(1, 1); issueA(2, 2);

    // prefetch skip rows into L2 during mainloop A
    {
        const float* pf = xskip + (size_t)(rb + (tid >> 2)) * 256 + (tid & 3) * 64;
        asm volatile("prefetch.global.L2 [%0];" :: "l"(pf));
        asm volatile("prefetch.global.L2 [%0];" :: "l"(pf + 32));
    }

    // ---- mainloop A: ctx @ Wo ----
#pragma unroll 1
    for (int kc = 0; kc < 16; kc++) {
        if (kc < 14)       { asm volatile("cp.async.wait_group 2;" ::: "memory"); }
        else if (kc == 14) { asm volatile("cp.async.wait_group 1;" ::: "memory"); }
        else               { asm volatile("cp.async.wait_group 0;" ::: "memory"); }
        __syncthreads();
        if (kc + 3 < 16) issueA(kc + 3, (kc + 3) & 3);
        const float* Ab = As + (kc & 3) * 1024;
        const float* Bb = Bs + (kc & 3) * 4096;
#pragma unroll
        for (int kh = 0; kh < 2; kh++) {
            int ka = (kh * 8 + tig) ^ swz;
            int kb2 = ka ^ 4;
            uint32_t af[2][4], bf[8][2];
#pragma unroll
            for (int mt = 0; mt < 2; mt++) {
                int mbase = (wm + mt * 16 + gid) * 16;
                af[mt][0] = __float_as_uint(Ab[mbase + ka]);
                af[mt][1] = __float_as_uint(Ab[mbase + 128 + ka]);
                af[mt][2] = __float_as_uint(Ab[mbase + kb2]);
                af[mt][3] = __float_as_uint(Ab[mbase + 128 + kb2]);
            }
#pragma unroll
            for (int nt = 0; nt < 8; nt++) {
                int nbase = (wn + nt * 8 + gid) * 16;
                bf[nt][0] = __float_as_uint(Bb[nbase + ka]);
                bf[nt][1] = __float_as_uint(Bb[nbase + kb2]);
            }
#pragma unroll
            for (int mt = 0; mt < 2; mt++)
#pragma unroll
                for (int nt = 0; nt < 8; nt++) {
                    asm volatile(
                        "mma.sync.aligned.m16n8k8.row.col.f32.tf32.tf32.f32 "
                        "{%0,%1,%2,%3}, {%4,%5,%6,%7}, {%8,%9}, {%0,%1,%2,%3};"
                        : "+f"(c[mt][nt][0]), "+f"(c[mt][nt][1]),
                          "+f"(c[mt][nt][2]), "+f"(c[mt][nt][3])
                        : "r"(af[mt][0]), "r"(af[mt][1]), "r"(af[mt][2]), "r"(af[mt][3]),
                          "r"(bf[nt][0]), "r"(bf[nt][1]));
                }
        }
    }
    __syncthreads();
    // start streaming Wout while the LN1 epilogue runs
    issueB(0, 0); issueB(1, 1); issueB(2, 2);

    // ---- LN1 epilogue: res -> A2 (SMEM) ----
#pragma unroll
    for (int mt = 0; mt < 2; mt++)
#pragma unroll
        for (int rr = 0; rr < 2; rr++) {
            int rl = wm + mt * 16 + gid + rr * 8;
            int gr = rb + rl;
            float psum = 0.f, psq = 0.f;
#pragma unroll
            for (int nt = 0; nt < 8; nt++) {
                int col = wn + nt * 8 + 2 * tig;
                float2 a2 = *(const float2*)(xskip + (size_t)gr * 256 + col);
                float v0 = c[mt][nt][rr * 2] + a2.x;
                float v1 = c[mt][nt][rr * 2 + 1] + a2.y;
                c[mt][nt][rr * 2] = v0; c[mt][nt][rr * 2 + 1] = v1;
                psum += v0 + v1;
                psq = fmaf(v0, v0, psq); psq = fmaf(v1, v1, psq);
            }
            psum += __shfl_xor_sync(0xffffffffu, psum, 1);
            psum += __shfl_xor_sync(0xffffffffu, psum, 2);
            psq  += __shfl_xor_sync(0xffffffffu, psq, 1);
            psq  += __shfl_xor_sync(0xffffffffu, psq, 2);
            if (tig == 0) { s_sum[rl][w >> 1] = psum; s_sq[rl][w >> 1] = psq; }
        }
    __syncthreads();
#pragma unroll
    for (int mt = 0; mt < 2; mt++)
#pragma unroll
        for (int rr = 0; rr < 2; rr++) {
            int rl = wm + mt * 16 + gid + rr * 8;
            float tot = s_sum[rl][0] + s_sum[rl][1] + s_sum[rl][2] + s_sum[rl][3];
            float tq  = s_sq[rl][0]  + s_sq[rl][1]  + s_sq[rl][2]  + s_sq[rl][3];
            float m = tot * (1.f / 256.f);
            float var = tq * (1.f / 256.f) - m * m;
            float inv = rsqrtf(var + 1e-5f);
            int rswz = 4 * ((rl >> 1) & 3);
#pragma unroll
            for (int nt = 0; nt < 8; nt++) {
                int col = wn + nt * 8 + 2 * tig;
                float o0 = tf32r((c[mt][nt][rr * 2]     - m) * inv * s_g1[col]     + s_b1[col]);
                float o1 = tf32r((c[mt][nt][rr * 2 + 1] - m) * inv * s_g1[col + 1] + s_b1[col + 1]);
                int chunk = col >> 4, kk = col & 15;
                *(float2*)&A2[chunk * 1024 + rl * 16 + (kk ^ rswz)] = make_float2(o0, o1);
            }
        }
    // reset accumulators for mainloop B
#pragma unroll
    for (int mt = 0; mt < 2; mt++)
#pragma unroll
        for (int nt = 0; nt < 8; nt++)
#pragma unroll
            for (int q = 0; q < 4; q++) c[mt][nt][q] = 0.f;
    __syncthreads();

    // ---- mainloop B: res @ Wout^T (A from SMEM A2) ----
#pragma unroll 1
    for (int kc = 0; kc < 16; kc++) {
        if (kc < 14)       { asm volatile("cp.async.wait_group 2;" ::: "memory"); }
        else if (kc == 14) { asm volatile("cp.async.wait_group 1;" ::: "memory"); }
        else               { asm volatile("cp.async.wait_group 0;" ::: "memory"); }
        __syncthreads();
        if (kc + 3 < 16) issueB(kc + 3, (kc + 3) & 3);
        const float* Ab = A2 + kc * 1024;
        const float* Bb = Bs + (kc & 3) * 4096;
#pragma unroll
        for (int kh = 0; kh < 2; kh++) {
            int ka = (kh * 8 + tig) ^ swz;
            int kb2 = ka ^ 4;
            uint32_t af[2][4], bf[8][2];
#pragma unroll
            for (int mt = 0; mt < 2; mt++) {
                int mbase = (wm + mt * 16 + gid) * 16;
                af[mt][0] = __float_as_uint(Ab[mbase + ka]);
                af[mt][1] = __float_as_uint(Ab[mbase + 128 + ka]);
                af[mt][2] = __float_as_uint(Ab[mbase + kb2]);
                af[mt][3] = __float_as_uint(Ab[mbase + 128 + kb2]);
            }
#pragma unroll
            for (int nt = 0; nt < 8; nt++) {
                int nbase = (wn + nt * 8 + gid) * 16;
                bf[nt][0] = __float_as_uint(Bb[nbase + ka]);
                bf[nt][1] = __float_as_uint(Bb[nbase + kb2]);
            }
#pragma unroll
            for (int mt = 0; mt < 2; mt++)
#pragma unroll
                for (int nt = 0; nt < 8; nt++) {
                    asm volatile(
                        "mma.sync.aligned.m16n8k8.row.col.f32.tf32.tf32.f32 "
                        "{%0,%1,%2,%3}, {%4,%5,%6,%7}, {%8,%9}, {%0,%1,%2,%3};"
                        : "+f"(c[mt][nt][0]), "+f"(c[mt][nt][1]),
                          "+f"(c[mt][nt][2]), "+f"(c[mt][nt][3])
                        : "r"(af[mt][0]), "r"(af[mt][1]), "r"(af[mt][2]), "r"(af[mt][3]),
                          "r"(bf[nt][0]), "r"(bf[nt][1]));
                }
        }
    }
    __syncthreads();

    // ---- LN2 + relu epilogue (residual from A2) ----
#pragma unroll
    for (int mt = 0; mt < 2; mt++)
#pragma unroll
        for (int rr = 0; rr < 2; rr++) {
            int rl = wm + mt * 16 + gid + rr * 8;
            int rswz = 4 * ((rl >> 1) & 3);
            float psum = 0.f, psq = 0.f;
#pragma unroll
            for (int nt = 0; nt < 8; nt++) {
                int col = wn + nt * 8 + 2 * tig;
                int chunk = col >> 4, kk = col & 15;
                float2 r2 = *(const float2*)&A2[chunk * 1024 + rl * 16 + (kk ^ rswz)];
                float v0 = c[mt][nt][rr * 2]     + r2.x + s_bo[col];
                float v1 = c[mt][nt][rr * 2 + 1] + r2.y + s_bo[col + 1];
                c[mt][nt][rr * 2] = v0; c[mt][nt][rr * 2 + 1] = v1;
                psum += v0 + v1;
                psq = fmaf(v0, v0, psq); psq = fmaf(v1, v1, psq);
            }
            psum += __shfl_xor_sync(0xffffffffu, psum, 1);
            psum += __shfl_xor_sync(0xffffffffu, psum, 2);
            psq  += __shfl_xor_sync(0xffffffffu, psq, 1);
            psq  += __shfl_xor_sync(0xffffffffu, psq, 2);
            if (tig == 0) { s_sum[rl][w >> 1] = psum; s_sq[rl][w >> 1] = psq; }
        }
    __syncthreads();
#pragma unroll
    for (int mt = 0; mt < 2; mt++)
#pragma unroll
        for (int rr = 0; rr < 2; rr++) {
            int rl = wm + mt * 16 + gid + rr * 8;
            int gr = rb + rl;
            float tot = s_sum[rl][0] + s_sum[rl][1] + s_sum[rl][2] + s_sum[rl][3];
            float tq  = s_sq[rl][0]  + s_sq[rl][1]  + s_sq[rl][2]  + s_sq[rl][3];
            float m = tot * (1.f / 256.f);
            float var = tq * (1.f / 256.f) - m * m;
            float inv = rsqrtf(var + 1e-5f);
#pragma unroll
            for (int nt = 0; nt < 8; nt++) {
                int col = wn + nt * 8 + 2 * tig;
                float o0 = fmaxf((c[mt][nt][rr * 2]     - m) * inv * s_g2[col]     + s_b2[col], 0.f);
                float o1 = fmaxf((c[mt][nt][rr * 2 + 1] - m) * inv * s_g2[col + 1] + s_b2[col + 1], 0.f);
                *(float2*)(outp + (size_t)gr * 256 + col) = make_float2(o0, o1);
            }
        }
}

// ---------------- K3: score tables, vector-LDS layout (R10 known-good) ----------------
#define TROWS 32
#define HALO  48
#define HSTR  36
#define RSTR  288
#define TAB_SMEM ((HALO + 18) * RSTR * 4)

__global__ void __launch_bounds__(256) k_tables(void) {
    extern __shared__ float smt[];
    float* s_xk = smt;
    float* s_pq = smt + HALO * RSTR;
    float* s_pk = s_pq + 9 * RSTR;
    int b = blockIdx.y;
    int r0 = blockIdx.x * TROWS;
    int tid = threadIdx.x;

    for (int idx = tid; idx < HALO * 64; idx += 256) {
        int lr = idx >> 6, i4 = idx & 63;
        int c4 = i4 * 4;
        int gr = r0 - 8 + lr;
        float4 v = make_float4(0.f, 0.f, 0.f, 0.f);
        if (gr >= 0 && gr < PLEN)
            v = *(const float4*)(g_qkv + ((size_t)(b * PLEN + gr)) * 768 + 256 + c4);
        *(float4*)(s_xk + lr * RSTR + (c4 >> 5) * HSTR + (c4 & 31)) = v;
    }
    for (int idx = tid; idx < 9 * 64; idx += 256) {
        int w = idx >> 6, i4 = idx & 63;
        int c4 = i4 * 4;
        int so = (c4 >> 5) * HSTR + (c4 & 31);
        *(float4*)(s_pq + w * RSTR + so) = *(const float4*)(g_posqkv + w * 768 + c4);
        *(float4*)(s_pk + w * RSTR + so) = *(const float4*)(g_posqkv + w * 768 + 256 + c4);
    }
    __syncthreads();

    if (blockIdx.x == 0 && blockIdx.y == 0) {
        for (int t = tid; t < 648; t += 256) {
            int hh = t / 81, qi = (t / 9) % 9, ki = t % 9;
            const float* pq = s_pq + qi * RSTR + hh * HSTR;
            const float* pk = s_pk + ki * RSTR + hh * HSTR;
            float a0 = 0.f, a1 = 0.f;
#pragma unroll
            for (int i = 0; i < 16; i += 4) {
                float4 q4 = *(const float4*)(pq + i);
                float4 k4 = *(const float4*)(pk + i);
                a0 = fmaf(q4.x, k4.x, a0); a0 = fmaf(q4.y, k4.y, a0);
                a0 = fmaf(q4.z, k4.z, a0); a0 = fmaf(q4.w, k4.w, a0);
                float4 q5 = *(const float4*)(pq + 16 + i);
                float4 k5 = *(const float4*)(pk + 16 + i);
                a1 = fmaf(q5.x, k5.x, a1); a1 = fmaf(q5.y, k5.y, a1);
                a1 = fmaf(q5.z, k5.z, a1); a1 = fmaf(q5.w, k5.w, a1);
            }
            g_pp[t] = (a0 + a1) * ATT_SCALE;
        }
    }

    int h = tid & 7, lr = tid >> 3;
    int r = r0 + lr;
    if (r >= PLEN) return;
    size_t grow = (size_t)(b * PLEN + r);

    float xq[32];
    {
        const float* qrow = g_qkv + grow * 768 + h * HDIM;
#pragma unroll
        for (int i = 0; i < 32; i += 4) {
            float4 v = *(const float4*)(qrow + i);
            xq[i] = v.x; xq[i + 1] = v.y; xq[i + 2] = v.z; xq[i + 3] = v.w;
        }
    }
#pragma unroll
    for (int w = 0; w < 9; w++) {
        const float* pk = s_pk + w * RSTR + h * HSTR;
        float a0 = 0.f, a1 = 0.f;
#pragma unroll
        for (int i = 0; i < 16; i += 4) {
            float4 k4 = *(const float4*)(pk + i);
            a0 = fmaf(xq[i], k4.x, a0);      a0 = fmaf(xq[i + 1], k4.y, a0);
            a0 = fmaf(xq[i + 2], k4.z, a0);  a0 = fmaf(xq[i + 3], k4.w, a0);
            float4 k5 = *(const float4*)(pk + 16 + i);
            a1 = fmaf(xq[16 + i], k5.x, a1);     a1 = fmaf(xq[17 + i], k5.y, a1);
            a1 = fmaf(xq[18 + i], k5.z, a1);     a1 = fmaf(xq[19 + i], k5.w, a1);
        }
        g_R1[(grow * 8 + h) * 9 + w] = (a0 + a1) * ATT_SCALE;
    }
#pragma unroll
    for (int dd = 0; dd < 17; dd++) {
        int rr = r + dd - 8;
        float acc = 0.f;
        if (rr >= 0 && rr < PLEN) {
            const float* kd = s_xk + (lr + dd) * RSTR + h * HSTR;
            float a0 = 0.f, a1 = 0.f;
#pragma unroll
            for (int i = 0; i < 16; i += 4) {
                float4 k4 = *(const float4*)(kd + i);
                a0 = fmaf(xq[i], k4.x, a0);      a0 = fmaf(xq[i + 1], k4.y, a0);
                a0 = fmaf(xq[i + 2], k4.z, a0);  a0 = fmaf(xq[i + 3], k4.w, a0);
                float4 k5 = *(const float4*)(kd + 16 + i);
                a1 = fmaf(xq[16 + i], k5.x, a1);     a1 = fmaf(xq[17 + i], k5.y, a1);
                a1 = fmaf(xq[18 + i], k5.z, a1);     a1 = fmaf(xq[19 + i], k5.w, a1);
            }
            acc = a0 + a1;
        }
        g_XX[(grow * 8 + h) * 17 + dd] = acc * ATT_SCALE;
    }

    float xk[32];
    {
        const float* kk = s_xk + (lr + 8) * RSTR + h * HSTR;
#pragma unroll
        for (int i = 0; i < 32; i += 4) {
            float4 v = *(const float4*)(kk + i);
            xk[i] = v.x; xk[i + 1] = v.y; xk[i + 2] = v.z; xk[i + 3] = v.w;
        }
    }
#pragma unroll
    for (int w = 0; w < 9; w++) {
        const float* pq = s_pq + w * RSTR + h * HSTR;
        float a0 = 0.f, a1 = 0.f;
#pragma unroll
        for (int i = 0; i < 16; i += 4) {
            float4 q4 = *(const float4*)(pq + i);
            a0 = fmaf(q4.x, xk[i], a0);      a0 = fmaf(q4.y, xk[i + 1], a0);
            a0 = fmaf(q4.z, xk[i + 2], a0);  a0 = fmaf(q4.w, xk[i + 3], a0);
            float4 q5 = *(const float4*)(pq + 16 + i);
            a1 = fmaf(q5.x, xk[16 + i], a1);     a1 = fmaf(q5.y, xk[17 + i], a1);
            a1 = fmaf(q5.z, xk[18 + i], a1);     a1 = fmaf(q5.w, xk[19 + i], a1);
        }
        g_R2[(grow * 8 + h) * 9 + w] = (a0 + a1) * ATT_SCALE;
    }
}

// ---------------- K5: staged softmax + ctx (R10 known-good) ----------------
#define ATT_SMEM ((5440 + 2880 + 2880 + 648 + 2304 + 2304) * 4)

__global__ void __launch_bounds__(256) k_attn(void) {
    extern __shared__ float sma[];
    float* s_XX = sma;            // [40][8][17]
    float* s_R1 = s_XX + 5440;    // [40][8][9]
    float* s_R2 = s_R1 + 2880;    // [40][8][9]
    float* s_pp = s_R2 + 2880;    // [8][81]
    float* s_pv = s_pp + 648;     // [9][256]
    float* s_w  = s_pv + 2304;    // [32][8][9]
    int b = blockIdx.y;
    int n0 = blockIdx.x * 32;
    int tid = threadIdx.x;
    size_t base = (size_t)b * PLEN + n0;

    {
        const float4* g4 = (const float4*)(g_XX + base * 136);
        for (int i = tid; i < 1360; i += 256) ((float4*)s_XX)[i] = g4[i];
    }
    {
        const float4* g4 = (const float4*)(g_R1 + base * 72);
        for (int i = tid; i < 720; i += 256) ((float4*)s_R1)[i] = g4[i];
    }
    {
        const float4* g4 = (const float4*)(g_R2 + base * 72);
        for (int i = tid; i < 720; i += 256) ((float4*)s_R2)[i] = g4[i];
    }
    for (int i = tid; i < 648; i += 256) s_pp[i] = g_pp[i];
    for (int i = tid; i < 2304; i += 256)
        s_pv[i] = g_posqkv[(i >> 8) * 768 + 512 + (i & 255)];
    __syncthreads();

    {
        int wi = tid >> 3, h = tid & 7;
        float wsum[9];
#pragma unroll
        for (int k = 0; k < 9; k++) wsum[k] = 0.f;
#pragma unroll 1
        for (int qi = 0; qi < 9; qi++) {
            const float* xxp = s_XX + (wi + qi) * 136 + h * 17 + (8 - qi);
            const float* r1p = s_R1 + (wi + qi) * 72 + h * 9;
            const float* ppp = s_pp + h * 81 + qi * 9;
            float s[9], sum = 0.f;
#pragma unroll
            for (int ki = 0; ki < 9; ki++) {
                float v = xxp[ki] + r1p[ki]
                        + s_R2[(wi + ki) * 72 + h * 9 + qi] + ppp[ki];
                s[ki] = __expf(v);
                sum += s[ki];
            }
            float inv = 1.f / sum;
#pragma unroll
            for (int ki = 0; ki < 9; ki++) wsum[ki] = fmaf(s[ki], inv, wsum[ki]);
        }
#pragma unroll
        for (int ki = 0; ki < 9; ki++) s_w[wi * 72 + h * 9 + ki] = wsum[ki];
    }
    __syncthreads();

    {
        int j = tid, h = j >> 5;
        float pv[9];
#pragma unroll
        for (int k = 0; k < 9; k++) pv[k] = s_pv[k * 256 + j];
        float acc[32];
#pragma unroll
        for (int wi = 0; wi < 32; wi++) acc[wi] = 0.f;
        const float* vcol = g_qkv + base * 768 + 512 + j;
        const float* wb = s_w + h * 9;
#pragma unroll
        for (int rr = 0; rr < 40; rr++) {
            float v = vcol[(size_t)rr * 768];
            int klo = (rr > 31) ? (rr - 31) : 0;
            int khi = (rr < 8) ? rr : 8;
#pragma unroll
            for (int k = klo; k <= khi; k++) {
                int wi = rr - k;
                acc[wi] = fmaf(wb[wi * 72 + k], v + pv[k], acc[wi]);
            }
        }
#pragma unroll
        for (int wi = 0; wi < 32; wi++)
            g_ctx[((size_t)b * LSEQ + n0 + wi) * 256 + j] = tf32r(acc[wi]);
    }
}

// ---------------- launch ----------------
extern "C" void kernel_launch(void* const* d_in, const int* in_sizes, int n_in,
                              void* d_out, int out_size) {
    const float* x    = (const float*)d_in[0];
    const float* Wq   = (const float*)d_in[1];
    const float* Wk   = (const float*)d_in[2];
    const float* Wv   = (const float*)d_in[3];
    const float* Wo   = (const float*)d_in[4];
    const float* pos  = (const float*)d_in[5];
    const float* Wout = (const float*)d_in[6];
    const float* bout = (const float*)d_in[7];
    const float* g1   = (const float*)d_in[8];
    const float* b1   = (const float*)d_in[9];
    const float* g2   = (const float*)d_in[10];
    const float* b2   = (const float*)d_in[11];
    float* out = (float*)d_out;

    const int GSM0 = (4 * 2048 + 4 * 4096) * 4;   // 96KB

    cudaFuncSetAttribute(k_tables, cudaFuncAttributeMaxDynamicSharedMemorySize, TAB_SMEM);
    cudaFuncSetAttribute(k_attn,   cudaFuncAttributeMaxDynamicSharedMemorySize, ATT_SMEM);
    cudaFuncSetAttribute(k_tgemm0, cudaFuncAttributeMaxDynamicSharedMemorySize, GSM0);
    cudaFuncSetAttribute(k_tail,   cudaFuncAttributeMaxDynamicSharedMemorySize, TAIL_SMEM);

    k_prep<<<8539, 256>>>(x, Wq, Wk, Wv, Wo, Wout, pos);

    {
        float* axr;
        cudaGetSymbolAddress((void**)&axr, g_xr);
        k_tgemm0<<<dim3(257, 3), 256, GSM0>>>(axr);
    }

    k_tables<<<dim3(257, NB), 256, TAB_SMEM>>>();
    k_attn<<<dim3(256, NB), 256, ATT_SMEM>>>();

    {
        float* actx;
        cudaGetSymbolAddress((void**)&actx, g_ctx);
        k_tail<<<512, 256, TAIL_SMEM>>>(actx, x, bout, g1, b1, g2, b2, out);
    }
}

// round 16
// speedup vs baseline: 1.0097x; 1.0097x over previous
#include <cuda_runtime.h>
#include <cstdint>
#include <math.h>

// ---------------- problem constants ----------------
#define NB     4
#define LSEQ   8192
#define DMODEL 256
#define NHEAD  8
#define HDIM   32
#define WNW    9
#define PAD    4
#define PLEN   8200          // L + 2*PAD
#define NROW   32800         // NB * PLEN
#define MROW   32768         // NB * LSEQ
#define ATT_SCALE 0.17677669529663687f  // 1/sqrt(32)

// ---------------- scratch ----------------
__device__ float g_qkv[(size_t)NROW * 768];
__device__ float g_posqkv[WNW * 768];
__device__ float g_pp[NHEAD * 81];
__device__ float g_R1[(size_t)NROW * NHEAD * 9];
__device__ float g_R2[(size_t)NROW * NHEAD * 9];
__device__ float g_XX[(size_t)NROW * NHEAD * 17];
__device__ float g_ctx[(size_t)MROW * DMODEL];
__device__ float g_wT[5 * 256 * 256];
__device__ float g_xr[(size_t)MROW * DMODEL];

__device__ __forceinline__ float tf32r(float x) {
    uint32_t u;
    asm("cvt.rna.tf32.f32 %0, %1;" : "=r"(u) : "f"(x));
    return __uint_as_float(u);
}
__device__ __forceinline__ uint32_t smem_u32(const void* p) {
    uint32_t a;
    asm("{ .reg .u64 t; cvta.to.shared.u64 t, %1; cvt.u32.u64 %0, t; }" : "=r"(a) : "l"(p));
    return a;
}

// ---------------- K_prep: round x + transpose/round weights + posproj ----------------
__global__ void __launch_bounds__(256) k_prep(const float* __restrict__ x,
                                              const float* __restrict__ Wq,
                                              const float* __restrict__ Wk,
                                              const float* __restrict__ Wv,
                                              const float* __restrict__ Wo,
                                              const float* __restrict__ Wout,
                                              const float* __restrict__ pos) {
    __shared__ float t[32][33];
    int bid = blockIdx.x;
    int tid = threadIdx.x;
    if (bid < 8192) {
        size_t i = ((size_t)bid * 256 + tid) * 4;
        float4 v = *(const float4*)(x + i);
        v.x = tf32r(v.x); v.y = tf32r(v.y); v.z = tf32r(v.z); v.w = tf32r(v.w);
        *(float4*)(g_xr + i) = v;
        return;
    }
    if (bid < 8512) {
        int rem = bid - 8192;
        int z = rem >> 6;
        int r2 = rem & 63;
        int bx = (r2 & 7) * 32, by = (r2 >> 3) * 32;
        int c = tid & 31, r0 = tid >> 5;
        if (z == 4) {
#pragma unroll
            for (int i = 0; i < 4; i++) {
                int r = r0 + i * 8;
                size_t idx = (size_t)(by + r) * 256 + bx + c;
                g_wT[(size_t)4 * 65536 + idx] = tf32r(Wout[idx]);
            }
            return;
        }
        const float* W = (z == 0) ? Wq : (z == 1) ? Wk : (z == 2) ? Wv : Wo;
#pragma unroll
        for (int i = 0; i < 4; i++) {
            int r = r0 + i * 8;
            t[r][c] = W[(size_t)(by + r) * 256 + bx + c];
        }
        __syncthreads();
#pragma unroll
        for (int i = 0; i < 4; i++) {
            int r = r0 + i * 8;
            g_wT[(size_t)z * 65536 + (size_t)(bx + r) * 256 + by + c] = tf32r(t[c][r]);
        }
        return;
    }
    int tt = (bid - 8512) * 256 + tid;
    int w = tt / 768, j = tt % 768;
    const float* W = (j < 256) ? Wq : ((j < 512) ? Wk : Wv);
    int jj = j & 255;
    const float* p = pos + w * DMODEL;
    float acc = 0.f;
    for (int d = 0; d < DMODEL; d++) acc = fmaf(p[d], W[d * DMODEL + jj], acc);
    g_posqkv[tt] = acc;
}

// ---------------- qkv projection GEMM (ybase selects which W / output columns) ----------------
__global__ void __launch_bounds__(256) k_tgemm0(const float* __restrict__ Aglob, int ybase) {
    constexpr int MT = 128;
    extern __shared__ float sm[];
    float* As = sm;                        // [4][2048]
    float* Bs = sm + 4 * 2048;             // [4][4096]
    int tid = threadIdx.x;
    int rb = blockIdx.x * MT;
    int yb = ybase + blockIdx.y;
    const float* Bmat = g_wT + (size_t)yb * 65536;

    const float* ap[2]; uint32_t azf[2]; uint32_t aAddr[2];
    const float* bp[4]; uint32_t bAddr[4];
#pragma unroll
    for (int i = 0; i < 2; i++) {
        int id = tid + i * 256;
        int row = id >> 2, c4 = (id & 3) * 4;
        int soff = row * 16 + (c4 ^ (4 * ((row >> 1) & 3)));
        aAddr[i] = smem_u32(&As[soff]);
        int gr = rb + row;
        int b = gr / PLEN;
        int r = gr - b * PLEN;
        int xr = r - PAD;
        bool av = (gr < NROW) && ((unsigned)xr < (unsigned)LSEQ);
        azf[i] = av ? 16u : 0u;
        ap[i] = Aglob + ((size_t)b * LSEQ + (size_t)((unsigned)xr < (unsigned)LSEQ ? xr : 0)) * 256 + c4;
    }
#pragma unroll
    for (int i = 0; i < 4; i++) {
        int id = tid + i * 256;
        int row = id >> 2, c4 = (id & 3) * 4;
        int soff = row * 16 + (c4 ^ (4 * ((row >> 1) & 3)));
        bAddr[i] = smem_u32(&Bs[soff]);
        bp[i] = Bmat + (size_t)row * 256 + c4;
    }

    auto issue = [&](int chunk, int stage) {
        int kb = chunk * 16;
        uint32_t ao = (uint32_t)stage * 8192;
        uint32_t bo = (uint32_t)stage * 16384;
#pragma unroll
        for (int i = 0; i < 2; i++)
            asm volatile("cp.async.cg.shared.global [%0], [%1], 16, %2;"
                         :: "r"(aAddr[i] + ao), "l"(ap[i] + kb), "r"(azf[i]) : "memory");
#pragma unroll
        for (int i = 0; i < 4; i++)
            asm volatile("cp.async.cg.shared.global [%0], [%1], 16;"
                         :: "r"(bAddr[i] + bo), "l"(bp[i] + kb) : "memory");
        asm volatile("cp.async.commit_group;" ::: "memory");
    };

    int lane = tid & 31;
    int w = tid >> 5;
    int wm = (w & 1) * 64;
    int wn = (w >> 1) * 64;
    int gid = lane >> 2;
    int tig = lane & 3;
    int swz = 4 * ((gid >> 1) & 3);

    float c[4][8][4];
#pragma unroll
    for (int mt = 0; mt < 4; mt++)
#pragma unroll
        for (int nt = 0; nt < 8; nt++)
#pragma unroll
            for (int q = 0; q < 4; q++) c[mt][nt][q] = 0.f;

    issue(0, 0); issue(1, 1); issue(2, 2);

#pragma unroll 1
    for (int kc = 0; kc < 16; kc++) {
        if (kc < 14)       { asm volatile("cp.async.wait_group 2;" ::: "memory"); }
        else if (kc == 14) { asm volatile("cp.async.wait_group 1;" ::: "memory"); }
        else               { asm volatile("cp.async.wait_group 0;" ::: "memory"); }
        __syncthreads();
        if (kc + 3 < 16) issue(kc + 3, (kc + 3) & 3);
        const float* Ab = As + (kc & 3) * 2048;
        const float* Bb = Bs + (kc & 3) * 4096;
#pragma unroll
        for (int kh = 0; kh < 2; kh++) {
            int ka = (kh * 8 + tig) ^ swz;
            int kb2 = ka ^ 4;
            uint32_t af[4][4], bf[8][2];
#pragma unroll
            for (int mt = 0; mt < 4; mt++) {
                int mbase = (wm + mt * 16 + gid) * 16;
                af[mt][0] = __float_as_uint(Ab[mbase + ka]);
                af[mt][1] = __float_as_uint(Ab[mbase + 128 + ka]);
                af[mt][2] = __float_as_uint(Ab[mbase + kb2]);
                af[mt][3] = __float_as_uint(Ab[mbase + 128 + kb2]);
            }
#pragma unroll
            for (int nt = 0; nt < 8; nt++) {
                int nbase = (wn + nt * 8 + gid) * 16;
                bf[nt][0] = __float_as_uint(Bb[nbase + ka]);
                bf[nt][1] = __float_as_uint(Bb[nbase + kb2]);
            }
#pragma unroll
            for (int mt = 0; mt < 4; mt++)
#pragma unroll
                for (int nt = 0; nt < 8; nt++) {
                    asm volatile(
                        "mma.sync.aligned.m16n8k8.row.col.f32.tf32.tf32.f32 "
                        "{%0,%1,%2,%3}, {%4,%5,%6,%7}, {%8,%9}, {%0,%1,%2,%3};"
                        : "+f"(c[mt][nt][0]), "+f"(c[mt][nt][1]),
                          "+f"(c[mt][nt][2]), "+f"(c[mt][nt][3])
                        : "r"(af[mt][0]), "r"(af[mt][1]), "r"(af[mt][2]), "r"(af[mt][3]),
                          "r"(bf[nt][0]), "r"(bf[nt][1]));
                }
        }
    }

    int jb = yb * 256;
#pragma unroll
    for (int mt = 0; mt < 4; mt++)
#pragma unroll
        for (int rr = 0; rr < 2; rr++) {
            int gr = rb + wm + mt * 16 + gid + rr * 8;
            if (gr >= NROW) continue;
#pragma unroll
            for (int nt = 0; nt < 8; nt++) {
                int col = wn + nt * 8 + 2 * tig;
                *(float2*)(g_qkv + (size_t)gr * 768 + jb + col) =
                    make_float2(c[mt][nt][rr * 2], c[mt][nt][rr * 2 + 1]);
            }
        }
}

// ---------------- K_tail: fused (x + ctx@Wo -> LN1) -> (res@Wout^T + bout + res -> LN2 -> relu) ----------------
#define TAIL_SMEM ((4 * 1024 + 4 * 4096 + 16384) * 4)

__global__ void __launch_bounds__(256) k_tail(const float* __restrict__ Actx,
                                              const float* __restrict__ xskip,
                                              const float* __restrict__ bout,
                                              const float* __restrict__ g1,
                                              const float* __restrict__ b1,
                                              const float* __restrict__ g2,
                                              const float* __restrict__ b2,
                                              float* __restrict__ outp) {
    extern __shared__ float sm[];
    float* As = sm;                 // [4][1024]
    float* Bs = sm + 4096;          // [4][4096]
    float* A2 = sm + 4096 + 16384;  // [16][64][16]
    __shared__ float s_g1[256], s_b1[256], s_g2[256], s_b2[256], s_bo[256];
    __shared__ float s_sum[64][4], s_sq[64][4];

    int tid = threadIdx.x;
    int rb = blockIdx.x * 64;
    s_g1[tid] = g1[tid]; s_b1[tid] = b1[tid];
    s_g2[tid] = g2[tid]; s_b2[tid] = b2[tid];
    s_bo[tid] = bout[tid];

    const float* ap; uint32_t aAddr;
    size_t boff[4]; uint32_t bAddr[4];
    {
        int row = tid >> 2, c4 = (tid & 3) * 4;
        int soff = row * 16 + (c4 ^ (4 * ((row >> 1) & 3)));
        aAddr = smem_u32(&As[soff]);
        ap = Actx + (size_t)(rb + row) * 256 + c4;
    }
    const float* BmatA = g_wT + (size_t)3 * 65536;   // Wo^T
    const float* BmatB = g_wT + (size_t)4 * 65536;   // Wout
#pragma unroll
    for (int i = 0; i < 4; i++) {
        int id = tid + i * 256;
        int row = id >> 2, c4 = (id & 3) * 4;
        int soff = row * 16 + (c4 ^ (4 * ((row >> 1) & 3)));
        bAddr[i] = smem_u32(&Bs[soff]);
        boff[i] = (size_t)row * 256 + c4;
    }

    auto issueA = [&](int chunk, int stage) {
        int kb = chunk * 16;
        uint32_t ao = (uint32_t)stage * 4096;
        uint32_t bo = (uint32_t)stage * 16384;
        asm volatile("cp.async.cg.shared.global [%0], [%1], 16;"
                     :: "r"(aAddr + ao), "l"(ap + kb) : "memory");
#pragma unroll
        for (int i = 0; i < 4; i++)
            asm volatile("cp.async.cg.shared.global [%0], [%1], 16;"
                         :: "r"(bAddr[i] + bo), "l"(BmatA + boff[i] + kb) : "memory");
        asm volatile("cp.async.commit_group;" ::: "memory");
    };
    auto issueB = [&](int chunk, int stage) {
        int kb = chunk * 16;
        uint32_t bo = (uint32_t)stage * 16384;
#pragma unroll
        for (int i = 0; i < 4; i++)
            asm volatile("cp.async.cg.shared.global [%0], [%1], 16;"
                         :: "r"(bAddr[i] + bo), "l"(BmatB + boff[i] + kb) : "memory");
        asm volatile("cp.async.commit_group;" ::: "memory");
    };

    int lane = tid & 31;
    int w = tid >> 5;
    int wm = (w & 1) * 32;
    int wn = (w >> 1) * 64;
    int gid = lane >> 2;
    int tig = lane & 3;
    int swz = 4 * ((gid >> 1) & 3);

    float c[2][8][4];
#pragma unroll
    for (int mt = 0; mt < 2; mt++)
#pragma unroll
        for (int nt = 0; nt < 8; nt++)
#pragma unroll
            for (int q = 0; q < 4; q++) c[mt][nt][q] = 0.f;

    issueA(0, 0); issueA(1, 1); issueA(2, 2);

    {
        const float* pf = xskip + (size_t)(rb + (tid >> 2)) * 256 + (tid & 3) * 64;
        asm volatile("prefetch.global.L2 [%0];" :: "l"(pf));
        asm volatile("prefetch.global.L2 [%0];" :: "l"(pf + 32));
    }

    // ---- mainloop A: ctx @ Wo ----
#pragma unroll 1
    for (int kc = 0; kc < 16; kc++) {
        if (kc < 14)       { asm volatile("cp.async.wait_group 2;" ::: "memory"); }
        else if (kc == 14) { asm volatile("cp.async.wait_group 1;" ::: "memory"); }
        else               { asm volatile("cp.async.wait_group 0;" ::: "memory"); }
        __syncthreads();
        if (kc + 3 < 16) issueA(kc + 3, (kc + 3) & 3);
        const float* Ab = As + (kc & 3) * 1024;
        const float* Bb = Bs + (kc & 3) * 4096;
#pragma unroll
        for (int kh = 0; kh < 2; kh++) {
            int ka = (kh * 8 + tig) ^ swz;
            int kb2 = ka ^ 4;
            uint32_t af[2][4], bf[8][2];
#pragma unroll
            for (int mt = 0; mt < 2; mt++) {
                int mbase = (wm + mt * 16 + gid) * 16;
                af[mt][0] = __float_as_uint(Ab[mbase + ka]);
                af[mt][1] = __float_as_uint(Ab[mbase + 128 + ka]);
                af[mt][2] = __float_as_uint(Ab[mbase + kb2]);
                af[mt][3] = __float_as_uint(Ab[mbase + 128 + kb2]);
            }
#pragma unroll
            for (int nt = 0; nt < 8; nt++) {
                int nbase = (wn + nt * 8 + gid) * 16;
                bf[nt][0] = __float_as_uint(Bb[nbase + ka]);
                bf[nt][1] = __float_as_uint(Bb[nbase + kb2]);
            }
#pragma unroll
            for (int mt = 0; mt < 2; mt++)
#pragma unroll
                for (int nt = 0; nt < 8; nt++) {
                    asm volatile(
                        "mma.sync.aligned.m16n8k8.row.col.f32.tf32.tf32.f32 "
                        "{%0,%1,%2,%3}, {%4,%5,%6,%7}, {%8,%9}, {%0,%1,%2,%3};"
                        : "+f"(c[mt][nt][0]), "+f"(c[mt][nt][1]),
                          "+f"(c[mt][nt][2]), "+f"(c[mt][nt][3])
                        : "r"(af[mt][0]), "r"(af[mt][1]), "r"(af[mt][2]), "r"(af[mt][3]),
                          "r"(bf[nt][0]), "r"(bf[nt][1]));
                }
        }
    }
    __syncthreads();
    issueB(0, 0); issueB(1, 1); issueB(2, 2);

    // ---- LN1 epilogue: res -> A2 (SMEM) ----
#pragma unroll
    for (int mt = 0; mt < 2; mt++)
#pragma unroll
        for (int rr = 0; rr < 2; rr++) {
            int rl = wm + mt * 16 + gid + rr * 8;
            int gr = rb + rl;
            float psum = 0.f, psq = 0.f;
#pragma unroll
            for (int nt = 0; nt < 8; nt++) {
                int col = wn + nt * 8 + 2 * tig;
                float2 a2 = *(const float2*)(xskip + (size_t)gr * 256 + col);
                float v0 = c[mt][nt][rr * 2] + a2.x;
                float v1 = c[mt][nt][rr * 2 + 1] + a2.y;
                c[mt][nt][rr * 2] = v0; c[mt][nt][rr * 2 + 1] = v1;
                psum += v0 + v1;
                psq = fmaf(v0, v0, psq); psq = fmaf(v1, v1, psq);
            }
            psum += __shfl_xor_sync(0xffffffffu, psum, 1);
            psum += __shfl_xor_sync(0xffffffffu, psum, 2);
            psq  += __shfl_xor_sync(0xffffffffu, psq, 1);
            psq  += __shfl_xor_sync(0xffffffffu, psq, 2);
            if (tig == 0) { s_sum[rl][w >> 1] = psum; s_sq[rl][w >> 1] = psq; }
        }
    __syncthreads();
#pragma unroll
    for (int mt = 0; mt < 2; mt++)
#pragma unroll
        for (int rr = 0; rr < 2; rr++) {
            int rl = wm + mt * 16 + gid + rr * 8;
            float tot = s_sum[rl][0] + s_sum[rl][1] + s_sum[rl][2] + s_sum[rl][3];
            float tq  = s_sq[rl][0]  + s_sq[rl][1]  + s_sq[rl][2]  + s_sq[rl][3];
            float m = tot * (1.f / 256.f);
            float var = tq * (1.f / 256.f) - m * m;
            float inv = rsqrtf(var + 1e-5f);
            int rswz = 4 * ((rl >> 1) & 3);
#pragma unroll
            for (int nt = 0; nt < 8; nt++) {
                int col = wn + nt * 8 + 2 * tig;
                float o0 = tf32r((c[mt][nt][rr * 2]     - m) * inv * s_g1[col]     + s_b1[col]);
                float o1 = tf32r((c[mt][nt][rr * 2 + 1] - m) * inv * s_g1[col + 1] + s_b1[col + 1]);
                int chunk = col >> 4, kk = col & 15;
                *(float2*)&A2[chunk * 1024 + rl * 16 + (kk ^ rswz)] = make_float2(o0, o1);
            }
        }
#pragma unroll
    for (int mt = 0; mt < 2; mt++)
#pragma unroll
        for (int nt = 0; nt < 8; nt++)
#pragma unroll
            for (int q = 0; q < 4; q++) c[mt][nt][q] = 0.f;
    __syncthreads();

    // ---- mainloop B: res @ Wout^T (A from SMEM A2) ----
#pragma unroll 1
    for (int kc = 0; kc < 16; kc++) {
        if (kc < 14)       { asm volatile("cp.async.wait_group 2;" ::: "memory"); }
        else if (kc == 14) { asm volatile("cp.async.wait_group 1;" ::: "memory"); }
        else               { asm volatile("cp.async.wait_group 0;" ::: "memory"); }
        __syncthreads();
        if (kc + 3 < 16) issueB(kc + 3, (kc + 3) & 3);
        const float* Ab = A2 + kc * 1024;
        const float* Bb = Bs + (kc & 3) * 4096;
#pragma unroll
        for (int kh = 0; kh < 2; kh++) {
            int ka = (kh * 8 + tig) ^ swz;
            int kb2 = ka ^ 4;
            uint32_t af[2][4], bf[8][2];
#pragma unroll
            for (int mt = 0; mt < 2; mt++) {
                int mbase = (wm + mt * 16 + gid) * 16;
                af[mt][0] = __float_as_uint(Ab[mbase + ka]);
                af[mt][1] = __float_as_uint(Ab[mbase + 128 + ka]);
                af[mt][2] = __float_as_uint(Ab[mbase + kb2]);
                af[mt][3] = __float_as_uint(Ab[mbase + 128 + kb2]);
            }
#pragma unroll
            for (int nt = 0; nt < 8; nt++) {
                int nbase = (wn + nt * 8 + gid) * 16;
                bf[nt][0] = __float_as_uint(Bb[nbase + ka]);
                bf[nt][1] = __float_as_uint(Bb[nbase + kb2]);
            }
#pragma unroll
            for (int mt = 0; mt < 2; mt++)
#pragma unroll
                for (int nt = 0; nt < 8; nt++) {
                    asm volatile(
                        "mma.sync.aligned.m16n8k8.row.col.f32.tf32.tf32.f32 "
                        "{%0,%1,%2,%3}, {%4,%5,%6,%7}, {%8,%9}, {%0,%1,%2,%3};"
                        : "+f"(c[mt][nt][0]), "+f"(c[mt][nt][1]),
                          "+f"(c[mt][nt][2]), "+f"(c[mt][nt][3])
                        : "r"(af[mt][0]), "r"(af[mt][1]), "r"(af[mt][2]), "r"(af[mt][3]),
                          "r"(bf[nt][0]), "r"(bf[nt][1]));
                }
        }
    }
    __syncthreads();

    // ---- LN2 + relu epilogue (residual from A2) ----
#pragma unroll
    for (int mt = 0; mt < 2; mt++)
#pragma unroll
        for (int rr = 0; rr < 2; rr++) {
            int rl = wm + mt * 16 + gid + rr * 8;
            int rswz = 4 * ((rl >> 1) & 3);
            float psum = 0.f, psq = 0.f;
#pragma unroll
            for (int nt = 0; nt < 8; nt++) {
                int col = wn + nt * 8 + 2 * tig;
                int chunk = col >> 4, kk = col & 15;
                float2 r2 = *(const float2*)&A2[chunk * 1024 + rl * 16 + (kk ^ rswz)];
                float v0 = c[mt][nt][rr * 2]     + r2.x + s_bo[col];
                float v1 = c[mt][nt][rr * 2 + 1] + r2.y + s_bo[col + 1];
                c[mt][nt][rr * 2] = v0; c[mt][nt][rr * 2 + 1] = v1;
                psum += v0 + v1;
                psq = fmaf(v0, v0, psq); psq = fmaf(v1, v1, psq);
            }
            psum += __shfl_xor_sync(0xffffffffu, psum, 1);
            psum += __shfl_xor_sync(0xffffffffu, psum, 2);
            psq  += __shfl_xor_sync(0xffffffffu, psq, 1);
            psq  += __shfl_xor_sync(0xffffffffu, psq, 2);
            if (tig == 0) { s_sum[rl][w >> 1] = psum; s_sq[rl][w >> 1] = psq; }
        }
    __syncthreads();
#pragma unroll
    for (int mt = 0; mt < 2; mt++)
#pragma unroll
        for (int rr = 0; rr < 2; rr++) {
            int rl = wm + mt * 16 + gid + rr * 8;
            int gr = rb + rl;
            float tot = s_sum[rl][0] + s_sum[rl][1] + s_sum[rl][2] + s_sum[rl][3];
            float tq  = s_sq[rl][0]  + s_sq[rl][1]  + s_sq[rl][2]  + s_sq[rl][3];
            float m = tot * (1.f / 256.f);
            float var = tq * (1.f / 256.f) - m * m;
            float inv = rsqrtf(var + 1e-5f);
#pragma unroll
            for (int nt = 0; nt < 8; nt++) {
                int col = wn + nt * 8 + 2 * tig;
                float o0 = fmaxf((c[mt][nt][rr * 2]     - m) * inv * s_g2[col]     + s_b2[col], 0.f);
                float o1 = fmaxf((c[mt][nt][rr * 2 + 1] - m) * inv * s_g2[col + 1] + s_b2[col + 1], 0.f);
                *(float2*)(outp + (size_t)gr * 256 + col) = make_float2(o0, o1);
            }
        }
}

// ---------------- K3: score tables, vector-LDS layout (R10 known-good) ----------------
#define TROWS 32
#define HALO  48
#define HSTR  36
#define RSTR  288
#define TAB_SMEM ((HALO + 18) * RSTR * 4)

__global__ void __launch_bounds__(256) k_tables(void) {
    extern __shared__ float smt[];
    float* s_xk = smt;
    float* s_pq = smt + HALO * RSTR;
    float* s_pk = s_pq + 9 * RSTR;
    int b = blockIdx.y;
    int r0 = blockIdx.x * TROWS;
    int tid = threadIdx.x;

    for (int idx = tid; idx < HALO * 64; idx += 256) {
        int lr = idx >> 6, i4 = idx & 63;
        int c4 = i4 * 4;
        int gr = r0 - 8 + lr;
        float4 v = make_float4(0.f, 0.f, 0.f, 0.f);
        if (gr >= 0 && gr < PLEN)
            v = *(const float4*)(g_qkv + ((size_t)(b * PLEN + gr)) * 768 + 256 + c4);
        *(float4*)(s_xk + lr * RSTR + (c4 >> 5) * HSTR + (c4 & 31)) = v;
    }
    for (int idx = tid; idx < 9 * 64; idx += 256) {
        int w = idx >> 6, i4 = idx & 63;
        int c4 = i4 * 4;
        int so = (c4 >> 5) * HSTR + (c4 & 31);
        *(float4*)(s_pq + w * RSTR + so) = *(const float4*)(g_posqkv + w * 768 + c4);
        *(float4*)(s_pk + w * RSTR + so) = *(const float4*)(g_posqkv + w * 768 + 256 + c4);
    }
    __syncthreads();

    if (blockIdx.x == 0 && blockIdx.y == 0) {
        for (int t = tid; t < 648; t += 256) {
            int hh = t / 81, qi = (t / 9) % 9, ki = t % 9;
            const float* pq = s_pq + qi * RSTR + hh * HSTR;
            const float* pk = s_pk + ki * RSTR + hh * HSTR;
            float a0 = 0.f, a1 = 0.f;
#pragma unroll
            for (int i = 0; i < 16; i += 4) {
                float4 q4 = *(const float4*)(pq + i);
                float4 k4 = *(const float4*)(pk + i);
                a0 = fmaf(q4.x, k4.x, a0); a0 = fmaf(q4.y, k4.y, a0);
                a0 = fmaf(q4.z, k4.z, a0); a0 = fmaf(q4.w, k4.w, a0);
                float4 q5 = *(const float4*)(pq + 16 + i);
                float4 k5 = *(const float4*)(pk + 16 + i);
                a1 = fmaf(q5.x, k5.x, a1); a1 = fmaf(q5.y, k5.y, a1);
                a1 = fmaf(q5.z, k5.z, a1); a1 = fmaf(q5.w, k5.w, a1);
            }
            g_pp[t] = (a0 + a1) * ATT_SCALE;
        }
    }

    int h = tid & 7, lr = tid >> 3;
    int r = r0 + lr;
    if (r >= PLEN) return;
    size_t grow = (size_t)(b * PLEN + r);

    float xq[32];
    {
        const float* qrow = g_qkv + grow * 768 + h * HDIM;
#pragma unroll
        for (int i = 0; i < 32; i += 4) {
            float4 v = *(const float4*)(qrow + i);
            xq[i] = v.x; xq[i + 1] = v.y; xq[i + 2] = v.z; xq[i + 3] = v.w;
        }
    }
#pragma unroll
    for (int w = 0; w < 9; w++) {
        const float* pk = s_pk + w * RSTR + h * HSTR;
        float a0 = 0.f, a1 = 0.f;
#pragma unroll
        for (int i = 0; i < 16; i += 4) {
            float4 k4 = *(const float4*)(pk + i);
            a0 = fmaf(xq[i], k4.x, a0);      a0 = fmaf(xq[i + 1], k4.y, a0);
            a0 = fmaf(xq[i + 2], k4.z, a0);  a0 = fmaf(xq[i + 3], k4.w, a0);
            float4 k5 = *(const float4*)(pk + 16 + i);
            a1 = fmaf(xq[16 + i], k5.x, a1);     a1 = fmaf(xq[17 + i], k5.y, a1);
            a1 = fmaf(xq[18 + i], k5.z, a1);     a1 = fmaf(xq[19 + i], k5.w, a1);
        }
        g_R1[(grow * 8 + h) * 9 + w] = (a0 + a1) * ATT_SCALE;
    }
#pragma unroll
    for (int dd = 0; dd < 17; dd++) {
        int rr = r + dd - 8;
        float acc = 0.f;
        if (rr >= 0 && rr < PLEN) {
            const float* kd = s_xk + (lr + dd) * RSTR + h * HSTR;
            float a0 = 0.f, a1 = 0.f;
#pragma unroll
            for (int i = 0; i < 16; i += 4) {
                float4 k4 = *(const float4*)(kd + i);
                a0 = fmaf(xq[i], k4.x, a0);      a0 = fmaf(xq[i + 1], k4.y, a0);
                a0 = fmaf(xq[i + 2], k4.z, a0);  a0 = fmaf(xq[i + 3], k4.w, a0);
                float4 k5 = *(const float4*)(kd + 16 + i);
                a1 = fmaf(xq[16 + i], k5.x, a1);     a1 = fmaf(xq[17 + i], k5.y, a1);
                a1 = fmaf(xq[18 + i], k5.z, a1);     a1 = fmaf(xq[19 + i], k5.w, a1);
            }
            acc = a0 + a1;
        }
        g_XX[(grow * 8 + h) * 17 + dd] = acc * ATT_SCALE;
    }

    float xk[32];
    {
        const float* kk = s_xk + (lr + 8) * RSTR + h * HSTR;
#pragma unroll
        for (int i = 0; i < 32; i += 4) {
            float4 v = *(const float4*)(kk + i);
            xk[i] = v.x; xk[i + 1] = v.y; xk[i + 2] = v.z; xk[i + 3] = v.w;
        }
    }
#pragma unroll
    for (int w = 0; w < 9; w++) {
        const float* pq = s_pq + w * RSTR + h * HSTR;
        float a0 = 0.f, a1 = 0.f;
#pragma unroll
        for (int i = 0; i < 16; i += 4) {
            float4 q4 = *(const float4*)(pq + i);
            a0 = fmaf(q4.x, xk[i], a0);      a0 = fmaf(q4.y, xk[i + 1], a0);
            a0 = fmaf(q4.z, xk[i + 2], a0);  a0 = fmaf(q4.w, xk[i + 3], a0);
            float4 q5 = *(const float4*)(pq + 16 + i);
            a1 = fmaf(q5.x, xk[16 + i], a1);     a1 = fmaf(q5.y, xk[17 + i], a1);
            a1 = fmaf(q5.z, xk[18 + i], a1);     a1 = fmaf(q5.w, xk[19 + i], a1);
        }
        g_R2[(grow * 8 + h) * 9 + w] = (a0 + a1) * ATT_SCALE;
    }
}

// ---------------- K5: staged softmax + ctx (R10 known-good) ----------------
#define ATT_SMEM ((5440 + 2880 + 2880 + 648 + 2304 + 2304) * 4)

__global__ void __launch_bounds__(256) k_attn(void) {
    extern __shared__ float sma[];
    float* s_XX = sma;            // [40][8][17]
    float* s_R1 = s_XX + 5440;    // [40][8][9]
    float* s_R2 = s_R1 + 2880;    // [40][8][9]
    float* s_pp = s_R2 + 2880;    // [8][81]
    float* s_pv = s_pp + 648;     // [9][256]
    float* s_w  = s_pv + 2304;    // [32][8][9]
    int b = blockIdx.y;
    int n0 = blockIdx.x * 32;
    int tid = threadIdx.x;
    size_t base = (size_t)b * PLEN + n0;

    {
        const float4* g4 = (const float4*)(g_XX + base * 136);
        for (int i = tid; i < 1360; i += 256) ((float4*)s_XX)[i] = g4[i];
    }
    {
        const float4* g4 = (const float4*)(g_R1 + base * 72);
        for (int i = tid; i < 720; i += 256) ((float4*)s_R1)[i] = g4[i];
    }
    {
        const float4* g4 = (const float4*)(g_R2 + base * 72);
        for (int i = tid; i < 720; i += 256) ((float4*)s_R2)[i] = g4[i];
    }
    for (int i = tid; i < 648; i += 256) s_pp[i] = g_pp[i];
    for (int i = tid; i < 2304; i += 256)
        s_pv[i] = g_posqkv[(i >> 8) * 768 + 512 + (i & 255)];
    __syncthreads();

    {
        int wi = tid >> 3, h = tid & 7;
        float wsum[9];
#pragma unroll
        for (int k = 0; k < 9; k++) wsum[k] = 0.f;
#pragma unroll 1
        for (int qi = 0; qi < 9; qi++) {
            const float* xxp = s_XX + (wi + qi) * 136 + h * 17 + (8 - qi);
            const float* r1p = s_R1 + (wi + qi) * 72 + h * 9;
            const float* ppp = s_pp + h * 81 + qi * 9;
            float s[9], sum = 0.f;
#pragma unroll
            for (int ki = 0; ki < 9; ki++) {
                float v = xxp[ki] + r1p[ki]
                        + s_R2[(wi + ki) * 72 + h * 9 + qi] + ppp[ki];
                s[ki] = __expf(v);
                sum += s[ki];
            }
            float inv = 1.f / sum;
#pragma unroll
            for (int ki = 0; ki < 9; ki++) wsum[ki] = fmaf(s[ki], inv, wsum[ki]);
        }
#pragma unroll
        for (int ki = 0; ki < 9; ki++) s_w[wi * 72 + h * 9 + ki] = wsum[ki];
    }
    __syncthreads();

    {
        int j = tid, h = j >> 5;
        float pv[9];
#pragma unroll
        for (int k = 0; k < 9; k++) pv[k] = s_pv[k * 256 + j];
        float acc[32];
#pragma unroll
        for (int wi = 0; wi < 32; wi++) acc[wi] = 0.f;
        const float* vcol = g_qkv + base * 768 + 512 + j;
        const float* wb = s_w + h * 9;
#pragma unroll
        for (int rr = 0; rr < 40; rr++) {
            float v = vcol[(size_t)rr * 768];
            int klo = (rr > 31) ? (rr - 31) : 0;
            int khi = (rr < 8) ? rr : 8;
#pragma unroll
            for (int k = klo; k <= khi; k++) {
                int wi = rr - k;
                acc[wi] = fmaf(wb[wi * 72 + k], v + pv[k], acc[wi]);
            }
        }
#pragma unroll
        for (int wi = 0; wi < 32; wi++)
            g_ctx[((size_t)b * LSEQ + n0 + wi) * 256 + j] = tf32r(acc[wi]);
    }
}

// ---------------- launch ----------------
extern "C" void kernel_launch(void* const* d_in, const int* in_sizes, int n_in,
                              void* d_out, int out_size) {
    const float* x    = (const float*)d_in[0];
    const float* Wq   = (const float*)d_in[1];
    const float* Wk   = (const float*)d_in[2];
    const float* Wv   = (const float*)d_in[3];
    const float* Wo   = (const float*)d_in[4];
    const float* pos  = (const float*)d_in[5];
    const float* Wout = (const float*)d_in[6];
    const float* bout = (const float*)d_in[7];
    const float* g1   = (const float*)d_in[8];
    const float* b1   = (const float*)d_in[9];
    const float* g2   = (const float*)d_in[10];
    const float* b2   = (const float*)d_in[11];
    float* out = (float*)d_out;

    const int GSM0 = (4 * 2048 + 4 * 4096) * 4;   // 96KB

    cudaFuncSetAttribute(k_tables, cudaFuncAttributeMaxDynamicSharedMemorySize, TAB_SMEM);
    cudaFuncSetAttribute(k_attn,   cudaFuncAttributeMaxDynamicSharedMemorySize, ATT_SMEM);
    cudaFuncSetAttribute(k_tgemm0, cudaFuncAttributeMaxDynamicSharedMemorySize, GSM0);
    cudaFuncSetAttribute(k_tail,   cudaFuncAttributeMaxDynamicSharedMemorySize, TAIL_SMEM);

    float* axr;  cudaGetSymbolAddress((void**)&axr, g_xr);
    float* actx; cudaGetSymbolAddress((void**)&actx, g_ctx);

    // fork/join stream for the V projection (only k_attn needs V).
    // Objects are intentionally not destroyed: they are referenced by the
    // captured graph; kernel_launch is invoked only a handful of times.
    cudaStream_t s2;
    cudaEvent_t eFork, eJoin;
    cudaStreamCreateWithFlags(&s2, cudaStreamNonBlocking);
    cudaEventCreateWithFlags(&eFork, cudaEventDisableTiming);
    cudaEventCreateWithFlags(&eJoin, cudaEventDisableTiming);

    k_prep<<<8539, 256>>>(x, Wq, Wk, Wv, Wo, Wout, pos);

    cudaEventRecord(eFork, 0);
    cudaStreamWaitEvent(s2, eFork, 0);

    // V projection on side stream (overlaps QK + tables)
    k_tgemm0<<<dim3(257, 1), 256, GSM0, s2>>>(axr, 2);
    cudaEventRecord(eJoin, s2);

    // QK projection + score tables on main stream
    k_tgemm0<<<dim3(257, 2), 256, GSM0>>>(axr, 0);
    k_tables<<<dim3(257, NB), 256, TAB_SMEM>>>();

    // join: attn needs V
    cudaStreamWaitEvent(0, eJoin, 0);
    k_attn<<<dim3(256, NB), 256, ATT_SMEM>>>();

    k_tail<<<512, 256, TAIL_SMEM>>>(actx, x, bout, g1, b1, g2, b2, out);
}